// round 1
// baseline (speedup 1.0000x reference)
#include <cuda_runtime.h>

#define S_LEN   2048
#define B_SZ    2
#define DM      1024
#define NH      16
#define HD      64
#define HK      1024            // NH*HD
#define MROWS   (B_SZ*S_LEN)    // 4096

// ---------------- scratch (static device arrays; no allocation) -------------
__device__ float g_q[B_SZ*NH*S_LEN*HD];   // (b,h,s,k) 16 MB
__device__ float g_k[B_SZ*NH*S_LEN*HD];
__device__ float g_v[B_SZ*NH*S_LEN*HD];
__device__ float g_o[MROWS*HK];           // (b,s,hk)  16 MB

// =====================================================================
// QKV projection: out[z] = x @ W[z] + b[z], written transposed to (b,h,s,k)
// 128x128x8 tiling, 256 threads, 8x8 per-thread micro-tile, reg prefetch.
// =====================================================================
__global__ __launch_bounds__(256, 2)
void qkv_gemm(const float* __restrict__ x,
              const float* __restrict__ Wq, const float* __restrict__ bq,
              const float* __restrict__ Wk, const float* __restrict__ bk,
              const float* __restrict__ Wv, const float* __restrict__ bv)
{
    __shared__ float As[8][128];   // [k][m] transposed
    __shared__ float Bs[8][128];   // [k][n]

    const float* W; const float* bias; float* out;
    int z = blockIdx.z;
    if (z == 0)      { W = Wq; bias = bq; out = g_q; }
    else if (z == 1) { W = Wk; bias = bk; out = g_k; }
    else             { W = Wv; bias = bv; out = g_v; }

    int tid = threadIdx.x;
    int tx = tid & 15, ty = tid >> 4;
    int m0 = blockIdx.y * 128, n0 = blockIdx.x * 128;

    int aRow = tid >> 1;            // 0..127
    int aCol = (tid & 1) * 4;       // 0 or 4
    int bRow = tid >> 5;            // 0..7
    int bCol = (tid & 31) * 4;      // 0..124

    const float* aPtr = x + (size_t)(m0 + aRow) * DM + aCol;
    const float* bPtr = W + (size_t)bRow * HK + n0 + bCol;

    float4 aReg = *(const float4*)aPtr;
    float4 bReg = *(const float4*)bPtr;

    float acc[8][8] = {};

    for (int k0 = 0; k0 < DM; k0 += 8) {
        As[aCol+0][aRow] = aReg.x;
        As[aCol+1][aRow] = aReg.y;
        As[aCol+2][aRow] = aReg.z;
        As[aCol+3][aRow] = aReg.w;
        *(float4*)&Bs[bRow][bCol] = bReg;
        __syncthreads();

        if (k0 + 8 < DM) {   // prefetch next slab while computing this one
            aReg = *(const float4*)(aPtr + (k0 + 8));
            bReg = *(const float4*)(bPtr + (size_t)(k0 + 8) * HK);
        }

        #pragma unroll
        for (int kk = 0; kk < 8; kk++) {
            float4 a0 = *(const float4*)&As[kk][ty*8];
            float4 a1 = *(const float4*)&As[kk][ty*8+4];
            float4 b0 = *(const float4*)&Bs[kk][tx*8];
            float4 b1 = *(const float4*)&Bs[kk][tx*8+4];
            float rm[8] = {a0.x,a0.y,a0.z,a0.w,a1.x,a1.y,a1.z,a1.w};
            float rn[8] = {b0.x,b0.y,b0.z,b0.w,b1.x,b1.y,b1.z,b1.w};
            #pragma unroll
            for (int i = 0; i < 8; i++)
                #pragma unroll
                for (int j = 0; j < 8; j++)
                    acc[i][j] = fmaf(rm[i], rn[j], acc[i][j]);
        }
        __syncthreads();
    }

    #pragma unroll
    for (int i = 0; i < 8; i++) {
        int m = m0 + ty*8 + i;
        int b = m >> 11, s = m & (S_LEN - 1);
        #pragma unroll
        for (int j = 0; j < 8; j++) {
            int n = n0 + tx*8 + j;
            int h = n >> 6, kd = n & 63;
            out[(((size_t)(b*NH + h) * S_LEN + s) << 6) + kd] = acc[i][j] + bias[n];
        }
    }
}

// =====================================================================
// Output projection: d_out = g_o @ Wo + bo   (4096 x 1024 x 1024)
// =====================================================================
__global__ __launch_bounds__(256, 2)
void out_gemm(const float* __restrict__ Wo,
              const float* __restrict__ bo,
              float* __restrict__ C)
{
    __shared__ float As[8][128];
    __shared__ float Bs[8][128];

    int tid = threadIdx.x;
    int tx = tid & 15, ty = tid >> 4;
    int m0 = blockIdx.y * 128, n0 = blockIdx.x * 128;

    int aRow = tid >> 1;
    int aCol = (tid & 1) * 4;
    int bRow = tid >> 5;
    int bCol = (tid & 31) * 4;

    const float* aPtr = g_o + (size_t)(m0 + aRow) * HK + aCol;
    const float* bPtr = Wo + (size_t)bRow * DM + n0 + bCol;

    float4 aReg = *(const float4*)aPtr;
    float4 bReg = *(const float4*)bPtr;

    float acc[8][8] = {};

    for (int k0 = 0; k0 < HK; k0 += 8) {
        As[aCol+0][aRow] = aReg.x;
        As[aCol+1][aRow] = aReg.y;
        As[aCol+2][aRow] = aReg.z;
        As[aCol+3][aRow] = aReg.w;
        *(float4*)&Bs[bRow][bCol] = bReg;
        __syncthreads();

        if (k0 + 8 < HK) {
            aReg = *(const float4*)(aPtr + (k0 + 8));
            bReg = *(const float4*)(bPtr + (size_t)(k0 + 8) * DM);
        }

        #pragma unroll
        for (int kk = 0; kk < 8; kk++) {
            float4 a0 = *(const float4*)&As[kk][ty*8];
            float4 a1 = *(const float4*)&As[kk][ty*8+4];
            float4 b0 = *(const float4*)&Bs[kk][tx*8];
            float4 b1 = *(const float4*)&Bs[kk][tx*8+4];
            float rm[8] = {a0.x,a0.y,a0.z,a0.w,a1.x,a1.y,a1.z,a1.w};
            float rn[8] = {b0.x,b0.y,b0.z,b0.w,b1.x,b1.y,b1.z,b1.w};
            #pragma unroll
            for (int i = 0; i < 8; i++)
                #pragma unroll
                for (int j = 0; j < 8; j++)
                    acc[i][j] = fmaf(rm[i], rn[j], acc[i][j]);
        }
        __syncthreads();
    }

    #pragma unroll
    for (int i = 0; i < 8; i++) {
        int m = m0 + ty*8 + i;
        #pragma unroll
        for (int j = 0; j < 8; j++) {
            int n = n0 + tx*8 + j;
            C[(size_t)m * DM + n] = acc[i][j] + bo[n];
        }
    }
}

// =====================================================================
// Fused flash attention, fp32.
// Block = 128 query rows of one (b,h). 256 threads (16x16).
// Per key tile (128 keys):
//   GEMM1: S = Q(128x64) @ K^T(64x128)  -> 8x8 regs/thread
//   online softmax in registers + half-warp shuffles (row-mates share ty)
//   P (exp'd) -> padded smem; GEMM2: O += P(128x128) @ V(128x64)
// =====================================================================
#define QK_STRIDE 132                      // pad: float4-aligned, low conflicts
#define ATTN_SMEM ((2*64*QK_STRIDE + 128*64 + 128*QK_STRIDE) * 4)

__global__ __launch_bounds__(256)
void attn_kernel()
{
    extern __shared__ float sm[];
    float* q_s = sm;                                   // [64][132]  (k, r)
    float* k_s = sm + 64*QK_STRIDE;                    // [64][132]  (k, j)
    float* v_s = sm + 2*64*QK_STRIDE;                  // [128][64]  (j, c)
    float* P_s = sm + 2*64*QK_STRIDE + 128*64;         // [128][132]

    int tid = threadIdx.x;
    int tx = tid & 15, ty = tid >> 4;
    int bh = blockIdx.y;
    const float* qp = g_q + (size_t)bh * S_LEN * HD;
    const float* kp = g_k + (size_t)bh * S_LEN * HD;
    const float* vp = g_v + (size_t)bh * S_LEN * HD;
    int r0 = blockIdx.x * 128;

    // load Q tile transposed: q_s[k][r]
    for (int idx = tid; idx < 128*64; idx += 256) {
        int r = idx >> 6, k = idx & 63;
        q_s[k*QK_STRIDE + r] = qp[(size_t)(r0 + r)*HD + k];
    }

    float o_acc[8][4];
    float m_r[8], l_r[8];
    #pragma unroll
    for (int i = 0; i < 8; i++) {
        m_r[i] = -1e30f; l_r[i] = 0.f;
        o_acc[i][0] = o_acc[i][1] = o_acc[i][2] = o_acc[i][3] = 0.f;
    }
    __syncthreads();

    for (int t0 = 0; t0 < S_LEN; t0 += 128) {
        // load K tile transposed and V tile
        for (int idx = tid; idx < 128*64; idx += 256) {
            int j = idx >> 6, k = idx & 63;
            float kv = kp[(size_t)(t0 + j)*HD + k];
            float vv = vp[(size_t)(t0 + j)*HD + k];
            k_s[k*QK_STRIDE + j] = kv;
            v_s[j*64 + k]        = vv;
        }
        __syncthreads();

        // ---- GEMM1: scores ----
        float acc[8][8] = {};
        #pragma unroll 8
        for (int kk = 0; kk < 64; kk++) {
            float4 a0 = *(const float4*)&q_s[kk*QK_STRIDE + ty*8];
            float4 a1 = *(const float4*)&q_s[kk*QK_STRIDE + ty*8 + 4];
            float4 b0 = *(const float4*)&k_s[kk*QK_STRIDE + tx*8];
            float4 b1 = *(const float4*)&k_s[kk*QK_STRIDE + tx*8 + 4];
            float rm[8] = {a0.x,a0.y,a0.z,a0.w,a1.x,a1.y,a1.z,a1.w};
            float rn[8] = {b0.x,b0.y,b0.z,b0.w,b1.x,b1.y,b1.z,b1.w};
            #pragma unroll
            for (int i = 0; i < 8; i++)
                #pragma unroll
                for (int j = 0; j < 8; j++)
                    acc[i][j] = fmaf(rm[i], rn[j], acc[i][j]);
        }

        // ---- online softmax (row spread across the 16 tx lanes of same ty) ----
        #pragma unroll
        for (int i = 0; i < 8; i++) {
            float s[8];
            float mx = -1e30f;
            #pragma unroll
            for (int j = 0; j < 8; j++) { s[j] = acc[i][j] * 0.125f; mx = fmaxf(mx, s[j]); }
            #pragma unroll
            for (int off = 8; off > 0; off >>= 1)
                mx = fmaxf(mx, __shfl_xor_sync(0xffffffffu, mx, off));
            float mnew  = fmaxf(m_r[i], mx);
            float alpha = __expf(m_r[i] - mnew);
            m_r[i] = mnew;
            float p[8]; float ps = 0.f;
            #pragma unroll
            for (int j = 0; j < 8; j++) { p[j] = __expf(s[j] - mnew); ps += p[j]; }
            #pragma unroll
            for (int off = 8; off > 0; off >>= 1)
                ps += __shfl_xor_sync(0xffffffffu, ps, off);
            l_r[i] = l_r[i]*alpha + ps;
            #pragma unroll
            for (int c = 0; c < 4; c++) o_acc[i][c] *= alpha;
            int row = ty*8 + i;
            *(float4*)&P_s[row*QK_STRIDE + tx*8]     = make_float4(p[0],p[1],p[2],p[3]);
            *(float4*)&P_s[row*QK_STRIDE + tx*8 + 4] = make_float4(p[4],p[5],p[6],p[7]);
        }
        __syncthreads();

        // ---- GEMM2: O += P @ V ----
        #pragma unroll 4
        for (int k4 = 0; k4 < 32; k4++) {
            float4 v0 = *(const float4*)&v_s[(k4*4+0)*64 + tx*4];
            float4 v1 = *(const float4*)&v_s[(k4*4+1)*64 + tx*4];
            float4 v2 = *(const float4*)&v_s[(k4*4+2)*64 + tx*4];
            float4 v3 = *(const float4*)&v_s[(k4*4+3)*64 + tx*4];
            #pragma unroll
            for (int i = 0; i < 8; i++) {
                float4 pp = *(const float4*)&P_s[(ty*8+i)*QK_STRIDE + k4*4];
                o_acc[i][0] = fmaf(pp.x, v0.x, o_acc[i][0]);
                o_acc[i][0] = fmaf(pp.y, v1.x, o_acc[i][0]);
                o_acc[i][0] = fmaf(pp.z, v2.x, o_acc[i][0]);
                o_acc[i][0] = fmaf(pp.w, v3.x, o_acc[i][0]);
                o_acc[i][1] = fmaf(pp.x, v0.y, o_acc[i][1]);
                o_acc[i][1] = fmaf(pp.y, v1.y, o_acc[i][1]);
                o_acc[i][1] = fmaf(pp.z, v2.y, o_acc[i][1]);
                o_acc[i][1] = fmaf(pp.w, v3.y, o_acc[i][1]);
                o_acc[i][2] = fmaf(pp.x, v0.z, o_acc[i][2]);
                o_acc[i][2] = fmaf(pp.y, v1.z, o_acc[i][2]);
                o_acc[i][2] = fmaf(pp.z, v2.z, o_acc[i][2]);
                o_acc[i][2] = fmaf(pp.w, v3.z, o_acc[i][2]);
                o_acc[i][3] = fmaf(pp.x, v0.w, o_acc[i][3]);
                o_acc[i][3] = fmaf(pp.y, v1.w, o_acc[i][3]);
                o_acc[i][3] = fmaf(pp.z, v2.w, o_acc[i][3]);
                o_acc[i][3] = fmaf(pp.w, v3.w, o_acc[i][3]);
            }
        }
        __syncthreads();
    }

    // epilogue -> g_o (b, s, h*64 + c)
    int b = bh >> 4, h = bh & 15;
    #pragma unroll
    for (int i = 0; i < 8; i++) {
        float inv = 1.0f / l_r[i];
        int r = r0 + ty*8 + i;
        float4 o4 = make_float4(o_acc[i][0]*inv, o_acc[i][1]*inv,
                                o_acc[i][2]*inv, o_acc[i][3]*inv);
        *(float4*)&g_o[(size_t)(b*S_LEN + r) * HK + h*64 + tx*4] = o4;
    }
}

// =====================================================================
extern "C" void kernel_launch(void* const* d_in, const int* in_sizes, int n_in,
                              void* d_out, int out_size)
{
    (void)in_sizes; (void)n_in; (void)out_size;
    const float* x  = (const float*)d_in[0];
    const float* Wq = (const float*)d_in[1];
    const float* bq = (const float*)d_in[2];
    const float* Wk = (const float*)d_in[3];
    const float* bk = (const float*)d_in[4];
    const float* Wv = (const float*)d_in[5];
    const float* bv = (const float*)d_in[6];
    const float* Wo = (const float*)d_in[7];
    const float* bo = (const float*)d_in[8];
    float* out = (float*)d_out;

    qkv_gemm<<<dim3(HK/128, MROWS/128, 3), 256>>>(x, Wq, bq, Wk, bk, Wv, bv);

    cudaFuncSetAttribute(attn_kernel, cudaFuncAttributeMaxDynamicSharedMemorySize, ATTN_SMEM);
    attn_kernel<<<dim3(S_LEN/128, B_SZ*NH), 256, ATTN_SMEM>>>();

    out_gemm<<<dim3(DM/128, MROWS/128), 256>>>(Wo, bo, out);
}

// round 2
// speedup vs baseline: 1.3459x; 1.3459x over previous
#include <cuda_runtime.h>

#define S_LEN   2048
#define B_SZ    2
#define DM      1024
#define NH      16
#define HD      64
#define HK      1024            // NH*HD
#define MROWS   (B_SZ*S_LEN)    // 4096

// ---------------- scratch (static device arrays; no allocation) -------------
__device__ float g_q[B_SZ*NH*S_LEN*HD];   // (b,h,s,k) 16 MB
__device__ float g_k[B_SZ*NH*S_LEN*HD];
__device__ float g_v[B_SZ*NH*S_LEN*HD];
__device__ float g_o[MROWS*HK];           // (b,s,hk)  16 MB

// ---------------- tf32 helpers ----------------------------------------------
__device__ __forceinline__ unsigned f2tf32(float f) {
    unsigned r;
    asm("cvt.rna.tf32.f32 %0, %1;" : "=r"(r) : "f"(f));
    return r;
}

__device__ __forceinline__ void mma_tf32(float* c, const unsigned* a, const unsigned* b) {
    asm volatile(
        "mma.sync.aligned.m16n8k8.row.col.f32.tf32.tf32.f32 "
        "{%0,%1,%2,%3}, {%4,%5,%6,%7}, {%8,%9}, {%0,%1,%2,%3};\n"
        : "+f"(c[0]), "+f"(c[1]), "+f"(c[2]), "+f"(c[3])
        : "r"(a[0]), "r"(a[1]), "r"(a[2]), "r"(a[3]),
          "r"(b[0]), "r"(b[1]));
}

// =====================================================================
// TF32 tensor-core GEMM core: 128x128x16 tile, 256 threads (8 warps 4x2),
// warp tile 32x64 (2 m16 tiles x 8 n8 tiles), m16n8k8 tf32 MMA.
// A in smem as [k][m], B as [k][n].
// =====================================================================
#define GS 132   // smem row stride (floats)

// QKV projection: out[z] = x @ W[z] + b[z], written transposed to (b,h,s,k)
__global__ __launch_bounds__(256, 2)
void qkv_gemm_tf32(const float* __restrict__ x,
                   const float* __restrict__ Wq, const float* __restrict__ bq,
                   const float* __restrict__ Wk, const float* __restrict__ bk,
                   const float* __restrict__ Wv, const float* __restrict__ bv)
{
    __shared__ unsigned As[16][GS];
    __shared__ unsigned Bs[16][GS];

    const float* W; const float* bias; float* out;
    int z = blockIdx.z;
    if (z == 0)      { W = Wq; bias = bq; out = g_q; }
    else if (z == 1) { W = Wk; bias = bk; out = g_k; }
    else             { W = Wv; bias = bv; out = g_v; }

    int tid  = threadIdx.x;
    int w    = tid >> 5, lane = tid & 31;
    int g    = lane >> 2, tig = lane & 3;
    int wm   = w & 3, wn = w >> 2;
    int m0   = blockIdx.y * 128, n0 = blockIdx.x * 128;

    // global->smem staging indices
    int aRow = tid >> 2;            // 0..63 (also +64)
    int aCol = (tid & 3) * 4;       // k offset 0/4/8/12
    int bRow = tid >> 5;            // 0..7 (also +8)
    int bCol = (tid & 31) * 4;

    const float* aPtr = x + (size_t)(m0 + aRow) * DM + aCol;
    const float* bPtr = W + (size_t)bRow * HK + n0 + bCol;

    float4 a0r = *(const float4*)aPtr;
    float4 a1r = *(const float4*)(aPtr + (size_t)64 * DM);
    float4 b0r = *(const float4*)bPtr;
    float4 b1r = *(const float4*)(bPtr + (size_t)8 * HK);

    float acc[2][8][4] = {};

    for (int k0 = 0; k0 < DM; k0 += 16) {
        As[aCol+0][aRow]    = f2tf32(a0r.x);
        As[aCol+1][aRow]    = f2tf32(a0r.y);
        As[aCol+2][aRow]    = f2tf32(a0r.z);
        As[aCol+3][aRow]    = f2tf32(a0r.w);
        As[aCol+0][aRow+64] = f2tf32(a1r.x);
        As[aCol+1][aRow+64] = f2tf32(a1r.y);
        As[aCol+2][aRow+64] = f2tf32(a1r.z);
        As[aCol+3][aRow+64] = f2tf32(a1r.w);
        Bs[bRow][bCol+0]    = f2tf32(b0r.x);
        Bs[bRow][bCol+1]    = f2tf32(b0r.y);
        Bs[bRow][bCol+2]    = f2tf32(b0r.z);
        Bs[bRow][bCol+3]    = f2tf32(b0r.w);
        Bs[bRow+8][bCol+0]  = f2tf32(b1r.x);
        Bs[bRow+8][bCol+1]  = f2tf32(b1r.y);
        Bs[bRow+8][bCol+2]  = f2tf32(b1r.z);
        Bs[bRow+8][bCol+3]  = f2tf32(b1r.w);
        __syncthreads();

        if (k0 + 16 < DM) {
            a0r = *(const float4*)(aPtr + (k0 + 16));
            a1r = *(const float4*)(aPtr + (size_t)64 * DM + (k0 + 16));
            b0r = *(const float4*)(bPtr + (size_t)(k0 + 16) * HK);
            b1r = *(const float4*)(bPtr + (size_t)(k0 + 24) * HK);
        }

        #pragma unroll
        for (int ks = 0; ks < 2; ks++) {
            int kb = ks * 8;
            unsigned af[2][4], bf[8][2];
            #pragma unroll
            for (int i = 0; i < 2; i++) {
                int mb = wm*32 + i*16;
                af[i][0] = As[kb+tig  ][mb+g];
                af[i][1] = As[kb+tig  ][mb+g+8];
                af[i][2] = As[kb+tig+4][mb+g];
                af[i][3] = As[kb+tig+4][mb+g+8];
            }
            #pragma unroll
            for (int j = 0; j < 8; j++) {
                int nb = wn*64 + j*8;
                bf[j][0] = Bs[kb+tig  ][nb+g];
                bf[j][1] = Bs[kb+tig+4][nb+g];
            }
            #pragma unroll
            for (int i = 0; i < 2; i++)
                #pragma unroll
                for (int j = 0; j < 8; j++)
                    mma_tf32(acc[i][j], af[i], bf[j]);
        }
        __syncthreads();
    }

    // epilogue -> transposed (b,h,s,k) with bias
    #pragma unroll
    for (int i = 0; i < 2; i++) {
        int r0m = m0 + wm*32 + i*16 + g;
        #pragma unroll
        for (int j = 0; j < 8; j++) {
            int n = n0 + wn*64 + j*8 + tig*2;
            int h = n >> 6, kd = n & 63;
            float bv0 = bias[n], bv1 = bias[n+1];
            int b0i = r0m >> 11, s0 = r0m & (S_LEN-1);
            size_t base0 = (((size_t)(b0i*NH + h) * S_LEN + s0) << 6) + kd;
            out[base0]     = acc[i][j][0] + bv0;
            out[base0 + 1] = acc[i][j][1] + bv1;
            int r1m = r0m + 8;
            int b1i = r1m >> 11, s1 = r1m & (S_LEN-1);
            size_t base1 = (((size_t)(b1i*NH + h) * S_LEN + s1) << 6) + kd;
            out[base1]     = acc[i][j][2] + bv0;
            out[base1 + 1] = acc[i][j][3] + bv1;
        }
    }
}

// Output projection: d_out = g_o @ Wo + bo   (4096 x 1024 x 1024)
__global__ __launch_bounds__(256, 2)
void out_gemm_tf32(const float* __restrict__ Wo,
                   const float* __restrict__ bo,
                   float* __restrict__ C)
{
    __shared__ unsigned As[16][GS];
    __shared__ unsigned Bs[16][GS];

    int tid  = threadIdx.x;
    int w    = tid >> 5, lane = tid & 31;
    int g    = lane >> 2, tig = lane & 3;
    int wm   = w & 3, wn = w >> 2;
    int m0   = blockIdx.y * 128, n0 = blockIdx.x * 128;

    int aRow = tid >> 2;
    int aCol = (tid & 3) * 4;
    int bRow = tid >> 5;
    int bCol = (tid & 31) * 4;

    const float* aPtr = g_o + (size_t)(m0 + aRow) * HK + aCol;
    const float* bPtr = Wo + (size_t)bRow * DM + n0 + bCol;

    float4 a0r = *(const float4*)aPtr;
    float4 a1r = *(const float4*)(aPtr + (size_t)64 * HK);
    float4 b0r = *(const float4*)bPtr;
    float4 b1r = *(const float4*)(bPtr + (size_t)8 * DM);

    float acc[2][8][4] = {};

    for (int k0 = 0; k0 < HK; k0 += 16) {
        As[aCol+0][aRow]    = f2tf32(a0r.x);
        As[aCol+1][aRow]    = f2tf32(a0r.y);
        As[aCol+2][aRow]    = f2tf32(a0r.z);
        As[aCol+3][aRow]    = f2tf32(a0r.w);
        As[aCol+0][aRow+64] = f2tf32(a1r.x);
        As[aCol+1][aRow+64] = f2tf32(a1r.y);
        As[aCol+2][aRow+64] = f2tf32(a1r.z);
        As[aCol+3][aRow+64] = f2tf32(a1r.w);
        Bs[bRow][bCol+0]    = f2tf32(b0r.x);
        Bs[bRow][bCol+1]    = f2tf32(b0r.y);
        Bs[bRow][bCol+2]    = f2tf32(b0r.z);
        Bs[bRow][bCol+3]    = f2tf32(b0r.w);
        Bs[bRow+8][bCol+0]  = f2tf32(b1r.x);
        Bs[bRow+8][bCol+1]  = f2tf32(b1r.y);
        Bs[bRow+8][bCol+2]  = f2tf32(b1r.z);
        Bs[bRow+8][bCol+3]  = f2tf32(b1r.w);
        __syncthreads();

        if (k0 + 16 < HK) {
            a0r = *(const float4*)(aPtr + (k0 + 16));
            a1r = *(const float4*)(aPtr + (size_t)64 * HK + (k0 + 16));
            b0r = *(const float4*)(bPtr + (size_t)(k0 + 16) * DM);
            b1r = *(const float4*)(bPtr + (size_t)(k0 + 24) * DM);
        }

        #pragma unroll
        for (int ks = 0; ks < 2; ks++) {
            int kb = ks * 8;
            unsigned af[2][4], bf[8][2];
            #pragma unroll
            for (int i = 0; i < 2; i++) {
                int mb = wm*32 + i*16;
                af[i][0] = As[kb+tig  ][mb+g];
                af[i][1] = As[kb+tig  ][mb+g+8];
                af[i][2] = As[kb+tig+4][mb+g];
                af[i][3] = As[kb+tig+4][mb+g+8];
            }
            #pragma unroll
            for (int j = 0; j < 8; j++) {
                int nb = wn*64 + j*8;
                bf[j][0] = Bs[kb+tig  ][nb+g];
                bf[j][1] = Bs[kb+tig+4][nb+g];
            }
            #pragma unroll
            for (int i = 0; i < 2; i++)
                #pragma unroll
                for (int j = 0; j < 8; j++)
                    mma_tf32(acc[i][j], af[i], bf[j]);
        }
        __syncthreads();
    }

    #pragma unroll
    for (int i = 0; i < 2; i++) {
        int r0m = m0 + wm*32 + i*16 + g;
        #pragma unroll
        for (int j = 0; j < 8; j++) {
            int n = n0 + wn*64 + j*8 + tig*2;
            float bv0 = bo[n], bv1 = bo[n+1];
            float2 o0 = make_float2(acc[i][j][0] + bv0, acc[i][j][1] + bv1);
            float2 o1 = make_float2(acc[i][j][2] + bv0, acc[i][j][3] + bv1);
            *(float2*)&C[(size_t)r0m * DM + n]       = o0;
            *(float2*)&C[(size_t)(r0m+8) * DM + n]   = o1;
        }
    }
}

// =====================================================================
// Fused flash attention, fp32 (unchanged from R1).
// =====================================================================
#define QK_STRIDE 132
#define ATTN_SMEM ((2*64*QK_STRIDE + 128*64 + 128*QK_STRIDE) * 4)

__global__ __launch_bounds__(256)
void attn_kernel()
{
    extern __shared__ float sm[];
    float* q_s = sm;                                   // [64][132]
    float* k_s = sm + 64*QK_STRIDE;                    // [64][132]
    float* v_s = sm + 2*64*QK_STRIDE;                  // [128][64]
    float* P_s = sm + 2*64*QK_STRIDE + 128*64;         // [128][132]

    int tid = threadIdx.x;
    int tx = tid & 15, ty = tid >> 4;
    int bh = blockIdx.y;
    const float* qp = g_q + (size_t)bh * S_LEN * HD;
    const float* kp = g_k + (size_t)bh * S_LEN * HD;
    const float* vp = g_v + (size_t)bh * S_LEN * HD;
    int r0 = blockIdx.x * 128;

    for (int idx = tid; idx < 128*64; idx += 256) {
        int r = idx >> 6, k = idx & 63;
        q_s[k*QK_STRIDE + r] = qp[(size_t)(r0 + r)*HD + k];
    }

    float o_acc[8][4];
    float m_r[8], l_r[8];
    #pragma unroll
    for (int i = 0; i < 8; i++) {
        m_r[i] = -1e30f; l_r[i] = 0.f;
        o_acc[i][0] = o_acc[i][1] = o_acc[i][2] = o_acc[i][3] = 0.f;
    }
    __syncthreads();

    for (int t0 = 0; t0 < S_LEN; t0 += 128) {
        for (int idx = tid; idx < 128*64; idx += 256) {
            int j = idx >> 6, k = idx & 63;
            float kv = kp[(size_t)(t0 + j)*HD + k];
            float vv = vp[(size_t)(t0 + j)*HD + k];
            k_s[k*QK_STRIDE + j] = kv;
            v_s[j*64 + k]        = vv;
        }
        __syncthreads();

        float acc[8][8] = {};
        #pragma unroll 8
        for (int kk = 0; kk < 64; kk++) {
            float4 a0 = *(const float4*)&q_s[kk*QK_STRIDE + ty*8];
            float4 a1 = *(const float4*)&q_s[kk*QK_STRIDE + ty*8 + 4];
            float4 b0 = *(const float4*)&k_s[kk*QK_STRIDE + tx*8];
            float4 b1 = *(const float4*)&k_s[kk*QK_STRIDE + tx*8 + 4];
            float rm[8] = {a0.x,a0.y,a0.z,a0.w,a1.x,a1.y,a1.z,a1.w};
            float rn[8] = {b0.x,b0.y,b0.z,b0.w,b1.x,b1.y,b1.z,b1.w};
            #pragma unroll
            for (int i = 0; i < 8; i++)
                #pragma unroll
                for (int j = 0; j < 8; j++)
                    acc[i][j] = fmaf(rm[i], rn[j], acc[i][j]);
        }

        #pragma unroll
        for (int i = 0; i < 8; i++) {
            float s[8];
            float mx = -1e30f;
            #pragma unroll
            for (int j = 0; j < 8; j++) { s[j] = acc[i][j] * 0.125f; mx = fmaxf(mx, s[j]); }
            #pragma unroll
            for (int off = 8; off > 0; off >>= 1)
                mx = fmaxf(mx, __shfl_xor_sync(0xffffffffu, mx, off));
            float mnew  = fmaxf(m_r[i], mx);
            float alpha = __expf(m_r[i] - mnew);
            m_r[i] = mnew;
            float p[8]; float ps = 0.f;
            #pragma unroll
            for (int j = 0; j < 8; j++) { p[j] = __expf(s[j] - mnew); ps += p[j]; }
            #pragma unroll
            for (int off = 8; off > 0; off >>= 1)
                ps += __shfl_xor_sync(0xffffffffu, ps, off);
            l_r[i] = l_r[i]*alpha + ps;
            #pragma unroll
            for (int c = 0; c < 4; c++) o_acc[i][c] *= alpha;
            int row = ty*8 + i;
            *(float4*)&P_s[row*QK_STRIDE + tx*8]     = make_float4(p[0],p[1],p[2],p[3]);
            *(float4*)&P_s[row*QK_STRIDE + tx*8 + 4] = make_float4(p[4],p[5],p[6],p[7]);
        }
        __syncthreads();

        #pragma unroll 4
        for (int k4 = 0; k4 < 32; k4++) {
            float4 v0 = *(const float4*)&v_s[(k4*4+0)*64 + tx*4];
            float4 v1 = *(const float4*)&v_s[(k4*4+1)*64 + tx*4];
            float4 v2 = *(const float4*)&v_s[(k4*4+2)*64 + tx*4];
            float4 v3 = *(const float4*)&v_s[(k4*4+3)*64 + tx*4];
            #pragma unroll
            for (int i = 0; i < 8; i++) {
                float4 pp = *(const float4*)&P_s[(ty*8+i)*QK_STRIDE + k4*4];
                o_acc[i][0] = fmaf(pp.x, v0.x, o_acc[i][0]);
                o_acc[i][0] = fmaf(pp.y, v1.x, o_acc[i][0]);
                o_acc[i][0] = fmaf(pp.z, v2.x, o_acc[i][0]);
                o_acc[i][0] = fmaf(pp.w, v3.x, o_acc[i][0]);
                o_acc[i][1] = fmaf(pp.x, v0.y, o_acc[i][1]);
                o_acc[i][1] = fmaf(pp.y, v1.y, o_acc[i][1]);
                o_acc[i][1] = fmaf(pp.z, v2.y, o_acc[i][1]);
                o_acc[i][1] = fmaf(pp.w, v3.y, o_acc[i][1]);
                o_acc[i][2] = fmaf(pp.x, v0.z, o_acc[i][2]);
                o_acc[i][2] = fmaf(pp.y, v1.z, o_acc[i][2]);
                o_acc[i][2] = fmaf(pp.z, v2.z, o_acc[i][2]);
                o_acc[i][2] = fmaf(pp.w, v3.z, o_acc[i][2]);
                o_acc[i][3] = fmaf(pp.x, v0.w, o_acc[i][3]);
                o_acc[i][3] = fmaf(pp.y, v1.w, o_acc[i][3]);
                o_acc[i][3] = fmaf(pp.z, v2.w, o_acc[i][3]);
                o_acc[i][3] = fmaf(pp.w, v3.w, o_acc[i][3]);
            }
        }
        __syncthreads();
    }

    int b = bh >> 4, h = bh & 15;
    #pragma unroll
    for (int i = 0; i < 8; i++) {
        float inv = 1.0f / l_r[i];
        int r = r0 + ty*8 + i;
        float4 o4 = make_float4(o_acc[i][0]*inv, o_acc[i][1]*inv,
                                o_acc[i][2]*inv, o_acc[i][3]*inv);
        *(float4*)&g_o[(size_t)(b*S_LEN + r) * HK + h*64 + tx*4] = o4;
    }
}

// =====================================================================
extern "C" void kernel_launch(void* const* d_in, const int* in_sizes, int n_in,
                              void* d_out, int out_size)
{
    (void)in_sizes; (void)n_in; (void)out_size;
    const float* x  = (const float*)d_in[0];
    const float* Wq = (const float*)d_in[1];
    const float* bq = (const float*)d_in[2];
    const float* Wk = (const float*)d_in[3];
    const float* bk = (const float*)d_in[4];
    const float* Wv = (const float*)d_in[5];
    const float* bv = (const float*)d_in[6];
    const float* Wo = (const float*)d_in[7];
    const float* bo = (const float*)d_in[8];
    float* out = (float*)d_out;

    qkv_gemm_tf32<<<dim3(HK/128, MROWS/128, 3), 256>>>(x, Wq, bq, Wk, bk, Wv, bv);

    cudaFuncSetAttribute(attn_kernel, cudaFuncAttributeMaxDynamicSharedMemorySize, ATTN_SMEM);
    attn_kernel<<<dim3(S_LEN/128, B_SZ*NH), 256, ATTN_SMEM>>>();

    out_gemm_tf32<<<dim3(DM/128, MROWS/128), 256>>>(Wo, bo, out);
}

// round 3
// speedup vs baseline: 2.1180x; 1.5738x over previous
#include <cuda_runtime.h>

#define S_LEN   2048
#define B_SZ    2
#define DM      1024
#define NH      16
#define HD      64
#define HK      1024            // NH*HD
#define MROWS   (B_SZ*S_LEN)    // 4096

// ---------------- scratch (static device arrays; no allocation) -------------
__device__ float g_q[B_SZ*NH*S_LEN*HD];   // (b,h,s,k) 16 MB
__device__ float g_k[B_SZ*NH*S_LEN*HD];
__device__ float g_v[B_SZ*NH*S_LEN*HD];
__device__ float g_o[MROWS*HK];           // (b,s,hk)  16 MB

// ---------------- tf32 helpers ----------------------------------------------
__device__ __forceinline__ unsigned f2tf32(float f) {
    unsigned r;
    asm("cvt.rna.tf32.f32 %0, %1;" : "=r"(r) : "f"(f));
    return r;
}

__device__ __forceinline__ void mma_tf32(float* c, const unsigned* a, const unsigned* b) {
    asm volatile(
        "mma.sync.aligned.m16n8k8.row.col.f32.tf32.tf32.f32 "
        "{%0,%1,%2,%3}, {%4,%5,%6,%7}, {%8,%9}, {%0,%1,%2,%3};\n"
        : "+f"(c[0]), "+f"(c[1]), "+f"(c[2]), "+f"(c[3])
        : "r"(a[0]), "r"(a[1]), "r"(a[2]), "r"(a[3]),
          "r"(b[0]), "r"(b[1]));
}

// =====================================================================
// TF32 tensor-core GEMM (unchanged from R2)
// =====================================================================
#define GS 132   // smem row stride

__global__ __launch_bounds__(256, 2)
void qkv_gemm_tf32(const float* __restrict__ x,
                   const float* __restrict__ Wq, const float* __restrict__ bq,
                   const float* __restrict__ Wk, const float* __restrict__ bk,
                   const float* __restrict__ Wv, const float* __restrict__ bv)
{
    __shared__ unsigned As[16][GS];
    __shared__ unsigned Bs[16][GS];

    const float* W; const float* bias; float* out;
    int z = blockIdx.z;
    if (z == 0)      { W = Wq; bias = bq; out = g_q; }
    else if (z == 1) { W = Wk; bias = bk; out = g_k; }
    else             { W = Wv; bias = bv; out = g_v; }

    int tid  = threadIdx.x;
    int w    = tid >> 5, lane = tid & 31;
    int g    = lane >> 2, tig = lane & 3;
    int wm   = w & 3, wn = w >> 2;
    int m0   = blockIdx.y * 128, n0 = blockIdx.x * 128;

    int aRow = tid >> 2;
    int aCol = (tid & 3) * 4;
    int bRow = tid >> 5;
    int bCol = (tid & 31) * 4;

    const float* aPtr = x + (size_t)(m0 + aRow) * DM + aCol;
    const float* bPtr = W + (size_t)bRow * HK + n0 + bCol;

    float4 a0r = *(const float4*)aPtr;
    float4 a1r = *(const float4*)(aPtr + (size_t)64 * DM);
    float4 b0r = *(const float4*)bPtr;
    float4 b1r = *(const float4*)(bPtr + (size_t)8 * HK);

    float acc[2][8][4] = {};

    for (int k0 = 0; k0 < DM; k0 += 16) {
        As[aCol+0][aRow]    = f2tf32(a0r.x);
        As[aCol+1][aRow]    = f2tf32(a0r.y);
        As[aCol+2][aRow]    = f2tf32(a0r.z);
        As[aCol+3][aRow]    = f2tf32(a0r.w);
        As[aCol+0][aRow+64] = f2tf32(a1r.x);
        As[aCol+1][aRow+64] = f2tf32(a1r.y);
        As[aCol+2][aRow+64] = f2tf32(a1r.z);
        As[aCol+3][aRow+64] = f2tf32(a1r.w);
        Bs[bRow][bCol+0]    = f2tf32(b0r.x);
        Bs[bRow][bCol+1]    = f2tf32(b0r.y);
        Bs[bRow][bCol+2]    = f2tf32(b0r.z);
        Bs[bRow][bCol+3]    = f2tf32(b0r.w);
        Bs[bRow+8][bCol+0]  = f2tf32(b1r.x);
        Bs[bRow+8][bCol+1]  = f2tf32(b1r.y);
        Bs[bRow+8][bCol+2]  = f2tf32(b1r.z);
        Bs[bRow+8][bCol+3]  = f2tf32(b1r.w);
        __syncthreads();

        if (k0 + 16 < DM) {
            a0r = *(const float4*)(aPtr + (k0 + 16));
            a1r = *(const float4*)(aPtr + (size_t)64 * DM + (k0 + 16));
            b0r = *(const float4*)(bPtr + (size_t)(k0 + 16) * HK);
            b1r = *(const float4*)(bPtr + (size_t)(k0 + 24) * HK);
        }

        #pragma unroll
        for (int ks = 0; ks < 2; ks++) {
            int kb = ks * 8;
            unsigned af[2][4], bf[8][2];
            #pragma unroll
            for (int i = 0; i < 2; i++) {
                int mb = wm*32 + i*16;
                af[i][0] = As[kb+tig  ][mb+g];
                af[i][1] = As[kb+tig  ][mb+g+8];
                af[i][2] = As[kb+tig+4][mb+g];
                af[i][3] = As[kb+tig+4][mb+g+8];
            }
            #pragma unroll
            for (int j = 0; j < 8; j++) {
                int nb = wn*64 + j*8;
                bf[j][0] = Bs[kb+tig  ][nb+g];
                bf[j][1] = Bs[kb+tig+4][nb+g];
            }
            #pragma unroll
            for (int i = 0; i < 2; i++)
                #pragma unroll
                for (int j = 0; j < 8; j++)
                    mma_tf32(acc[i][j], af[i], bf[j]);
        }
        __syncthreads();
    }

    #pragma unroll
    for (int i = 0; i < 2; i++) {
        int r0m = m0 + wm*32 + i*16 + g;
        #pragma unroll
        for (int j = 0; j < 8; j++) {
            int n = n0 + wn*64 + j*8 + tig*2;
            int h = n >> 6, kd = n & 63;
            float bv0 = bias[n], bv1 = bias[n+1];
            int b0i = r0m >> 11, s0 = r0m & (S_LEN-1);
            size_t base0 = (((size_t)(b0i*NH + h) * S_LEN + s0) << 6) + kd;
            out[base0]     = acc[i][j][0] + bv0;
            out[base0 + 1] = acc[i][j][1] + bv1;
            int r1m = r0m + 8;
            int b1i = r1m >> 11, s1 = r1m & (S_LEN-1);
            size_t base1 = (((size_t)(b1i*NH + h) * S_LEN + s1) << 6) + kd;
            out[base1]     = acc[i][j][2] + bv0;
            out[base1 + 1] = acc[i][j][3] + bv1;
        }
    }
}

__global__ __launch_bounds__(256, 2)
void out_gemm_tf32(const float* __restrict__ Wo,
                   const float* __restrict__ bo,
                   float* __restrict__ C)
{
    __shared__ unsigned As[16][GS];
    __shared__ unsigned Bs[16][GS];

    int tid  = threadIdx.x;
    int w    = tid >> 5, lane = tid & 31;
    int g    = lane >> 2, tig = lane & 3;
    int wm   = w & 3, wn = w >> 2;
    int m0   = blockIdx.y * 128, n0 = blockIdx.x * 128;

    int aRow = tid >> 2;
    int aCol = (tid & 3) * 4;
    int bRow = tid >> 5;
    int bCol = (tid & 31) * 4;

    const float* aPtr = g_o + (size_t)(m0 + aRow) * HK + aCol;
    const float* bPtr = Wo + (size_t)bRow * DM + n0 + bCol;

    float4 a0r = *(const float4*)aPtr;
    float4 a1r = *(const float4*)(aPtr + (size_t)64 * HK);
    float4 b0r = *(const float4*)bPtr;
    float4 b1r = *(const float4*)(bPtr + (size_t)8 * DM);

    float acc[2][8][4] = {};

    for (int k0 = 0; k0 < HK; k0 += 16) {
        As[aCol+0][aRow]    = f2tf32(a0r.x);
        As[aCol+1][aRow]    = f2tf32(a0r.y);
        As[aCol+2][aRow]    = f2tf32(a0r.z);
        As[aCol+3][aRow]    = f2tf32(a0r.w);
        As[aCol+0][aRow+64] = f2tf32(a1r.x);
        As[aCol+1][aRow+64] = f2tf32(a1r.y);
        As[aCol+2][aRow+64] = f2tf32(a1r.z);
        As[aCol+3][aRow+64] = f2tf32(a1r.w);
        Bs[bRow][bCol+0]    = f2tf32(b0r.x);
        Bs[bRow][bCol+1]    = f2tf32(b0r.y);
        Bs[bRow][bCol+2]    = f2tf32(b0r.z);
        Bs[bRow][bCol+3]    = f2tf32(b0r.w);
        Bs[bRow+8][bCol+0]  = f2tf32(b1r.x);
        Bs[bRow+8][bCol+1]  = f2tf32(b1r.y);
        Bs[bRow+8][bCol+2]  = f2tf32(b1r.z);
        Bs[bRow+8][bCol+3]  = f2tf32(b1r.w);
        __syncthreads();

        if (k0 + 16 < HK) {
            a0r = *(const float4*)(aPtr + (k0 + 16));
            a1r = *(const float4*)(aPtr + (size_t)64 * HK + (k0 + 16));
            b0r = *(const float4*)(bPtr + (size_t)(k0 + 16) * DM);
            b1r = *(const float4*)(bPtr + (size_t)(k0 + 24) * DM);
        }

        #pragma unroll
        for (int ks = 0; ks < 2; ks++) {
            int kb = ks * 8;
            unsigned af[2][4], bf[8][2];
            #pragma unroll
            for (int i = 0; i < 2; i++) {
                int mb = wm*32 + i*16;
                af[i][0] = As[kb+tig  ][mb+g];
                af[i][1] = As[kb+tig  ][mb+g+8];
                af[i][2] = As[kb+tig+4][mb+g];
                af[i][3] = As[kb+tig+4][mb+g+8];
            }
            #pragma unroll
            for (int j = 0; j < 8; j++) {
                int nb = wn*64 + j*8;
                bf[j][0] = Bs[kb+tig  ][nb+g];
                bf[j][1] = Bs[kb+tig+4][nb+g];
            }
            #pragma unroll
            for (int i = 0; i < 2; i++)
                #pragma unroll
                for (int j = 0; j < 8; j++)
                    mma_tf32(acc[i][j], af[i], bf[j]);
        }
        __syncthreads();
    }

    #pragma unroll
    for (int i = 0; i < 2; i++) {
        int r0m = m0 + wm*32 + i*16 + g;
        #pragma unroll
        for (int j = 0; j < 8; j++) {
            int n = n0 + wn*64 + j*8 + tig*2;
            float bv0 = bo[n], bv1 = bo[n+1];
            float2 o0 = make_float2(acc[i][j][0] + bv0, acc[i][j][1] + bv1);
            float2 o1 = make_float2(acc[i][j][2] + bv0, acc[i][j][3] + bv1);
            *(float2*)&C[(size_t)r0m * DM + n]       = o0;
            *(float2*)&C[(size_t)(r0m+8) * DM + n]   = o1;
        }
    }
}

// =====================================================================
// Flash attention on tf32 tensor cores.
// Block: 128 q rows of one (b,h), 256 threads (8 warps).
// Warp w owns q rows [16w, 16w+16) -> softmax is quad-local.
// Smem layouts are pre-swizzled B/A fragments:
//   KB [8 kt][16 nt][32 lane][2]  (K as B-operand of QK^T)
//   VB [16 kt][8 nt][32 lane][2]  (V as B-operand of P@V)
//   PA [8 warp][16 kt][32 lane][4] (P as A-operand of P@V)
// =====================================================================
#define ATTN_SMEM (32768 * 4)   // 128 KB

__global__ __launch_bounds__(256, 1)
void attn_mma()
{
    extern __shared__ unsigned su[];
    unsigned* KB = su;            // 8192
    unsigned* VB = su + 8192;     // 8192
    unsigned* PA = su + 16384;    // 16384

    int tid  = threadIdx.x;
    int w    = tid >> 5, lane = tid & 31;
    int g    = lane >> 2, tig = lane & 3;
    int bh   = blockIdx.y;
    int b    = bh >> 4, h = bh & 15;
    int q0   = blockIdx.x * 128;

    const float* qp = g_q + (size_t)bh * S_LEN * HD;
    const float* kp = g_k + (size_t)bh * S_LEN * HD;
    const float* vp = g_v + (size_t)bh * S_LEN * HD;

    // ---- stage Q tile (reuse PA region), then pin fragments in registers ----
    float* Qs = (float*)PA;    // [128][64]
    #pragma unroll
    for (int it = 0; it < 8; it++) {
        int linear = it*256 + tid;
        int j = linear >> 4, d0 = (linear & 15) * 4;
        *(float4*)&Qs[j*64 + d0] = *(const float4*)&qp[(size_t)(q0 + j)*HD + d0];
    }
    __syncthreads();
    unsigned qf[8][4];
    #pragma unroll
    for (int kt = 0; kt < 8; kt++) {
        qf[kt][0] = f2tf32(Qs[(16*w+g  )*64 + kt*8 + tig  ]);
        qf[kt][1] = f2tf32(Qs[(16*w+g+8)*64 + kt*8 + tig  ]);
        qf[kt][2] = f2tf32(Qs[(16*w+g  )*64 + kt*8 + tig+4]);
        qf[kt][3] = f2tf32(Qs[(16*w+g+8)*64 + kt*8 + tig+4]);
    }
    __syncthreads();

    float o_acc[8][4] = {};
    float m0 = -1e30f, m1 = -1e30f, l0 = 0.f, l1 = 0.f;

    for (int t0 = 0; t0 < S_LEN; t0 += 128) {
        // ---- stage K, V into fragment layouts ----
        #pragma unroll
        for (int it = 0; it < 8; it++) {
            int linear = it*256 + tid;
            int j = linear >> 4, d0 = (linear & 15) * 4;
            float4 kv = *(const float4*)&kp[(size_t)(t0+j)*HD + d0];
            {
                int kt = d0 >> 3, creg = (d0 >> 2) & 1;
                int nt = j >> 3, nin = j & 7;
                unsigned* dst = &KB[(((kt<<4)+nt)<<6) + (nin<<3) + creg];
                dst[0] = f2tf32(kv.x); dst[2] = f2tf32(kv.y);
                dst[4] = f2tf32(kv.z); dst[6] = f2tf32(kv.w);
            }
            float4 vv = *(const float4*)&vp[(size_t)(t0+j)*HD + d0];
            {
                int ktv = j >> 3, kin = j & 7;
                int ntv = d0 >> 3, nin0 = d0 & 7;      // 0 or 4
                unsigned* dv = &VB[(((ktv<<3)+ntv)<<6) + ((nin0*4 + (kin&3))<<1) + (kin>>2)];
                dv[0]  = f2tf32(vv.x); dv[8]  = f2tf32(vv.y);
                dv[16] = f2tf32(vv.z); dv[24] = f2tf32(vv.w);
            }
        }
        __syncthreads();

        // ---- S = Q @ K^T ----
        float s[16][4];
        #pragma unroll
        for (int nt = 0; nt < 16; nt++) { s[nt][0]=0.f; s[nt][1]=0.f; s[nt][2]=0.f; s[nt][3]=0.f; }
        #pragma unroll
        for (int kt = 0; kt < 8; kt++) {
            #pragma unroll
            for (int nt = 0; nt < 16; nt++) {
                unsigned b2[2];
                *(uint2*)b2 = *(const uint2*)&KB[(((kt<<4)+nt)<<6) + (lane<<1)];
                mma_tf32(s[nt], qf[kt], b2);
            }
        }

        // ---- online softmax (quad-local) ----
        float mx0 = m0, mx1 = m1;
        #pragma unroll
        for (int nt = 0; nt < 16; nt++) {
            mx0 = fmaxf(mx0, fmaxf(s[nt][0], s[nt][1]) * 0.125f);
            mx1 = fmaxf(mx1, fmaxf(s[nt][2], s[nt][3]) * 0.125f);
        }
        mx0 = fmaxf(mx0, __shfl_xor_sync(0xffffffffu, mx0, 1));
        mx0 = fmaxf(mx0, __shfl_xor_sync(0xffffffffu, mx0, 2));
        mx1 = fmaxf(mx1, __shfl_xor_sync(0xffffffffu, mx1, 1));
        mx1 = fmaxf(mx1, __shfl_xor_sync(0xffffffffu, mx1, 2));

        float alpha0 = __expf(m0 - mx0);
        float alpha1 = __expf(m1 - mx1);
        m0 = mx0; m1 = mx1;

        float sum0 = 0.f, sum1 = 0.f;
        unsigned* paw = PA + w*2048;
        #pragma unroll
        for (int nt = 0; nt < 16; nt++) {
            float p00 = __expf(s[nt][0]*0.125f - mx0);
            float p01 = __expf(s[nt][1]*0.125f - mx0);
            float p10 = __expf(s[nt][2]*0.125f - mx1);
            float p11 = __expf(s[nt][3]*0.125f - mx1);
            sum0 += p00 + p01;
            sum1 += p10 + p11;
            int c0 = 2*tig;                      // 0,2,4,6
            int regsel = (c0 < 4) ? 0 : 2;
            unsigned* base = &paw[((nt<<5) + 4*g + (c0&3)) * 4 + regsel];
            *(uint2*)base       = make_uint2(f2tf32(p00), f2tf32(p10));
            *(uint2*)(base + 4) = make_uint2(f2tf32(p01), f2tf32(p11));
        }
        sum0 += __shfl_xor_sync(0xffffffffu, sum0, 1);
        sum0 += __shfl_xor_sync(0xffffffffu, sum0, 2);
        sum1 += __shfl_xor_sync(0xffffffffu, sum1, 1);
        sum1 += __shfl_xor_sync(0xffffffffu, sum1, 2);
        l0 = l0*alpha0 + sum0;
        l1 = l1*alpha1 + sum1;

        #pragma unroll
        for (int nt = 0; nt < 8; nt++) {
            o_acc[nt][0] *= alpha0; o_acc[nt][1] *= alpha0;
            o_acc[nt][2] *= alpha1; o_acc[nt][3] *= alpha1;
        }
        __syncwarp();

        // ---- O += P @ V ----
        #pragma unroll
        for (int kt = 0; kt < 16; kt++) {
            unsigned pa[4];
            *(uint4*)pa = *(const uint4*)&paw[((kt<<5) + lane) * 4];
            #pragma unroll
            for (int nt = 0; nt < 8; nt++) {
                unsigned b2[2];
                *(uint2*)b2 = *(const uint2*)&VB[(((kt<<3)+nt)<<6) + (lane<<1)];
                mma_tf32(o_acc[nt], pa, b2);
            }
        }
        __syncthreads();
    }

    // ---- epilogue ----
    float inv0 = 1.0f / l0, inv1 = 1.0f / l1;
    int r0 = q0 + 16*w + g, r1 = r0 + 8;
    #pragma unroll
    for (int nt = 0; nt < 8; nt++) {
        int c = nt*8 + 2*tig;
        *(float2*)&g_o[(size_t)(b*S_LEN + r0)*HK + h*64 + c] =
            make_float2(o_acc[nt][0]*inv0, o_acc[nt][1]*inv0);
        *(float2*)&g_o[(size_t)(b*S_LEN + r1)*HK + h*64 + c] =
            make_float2(o_acc[nt][2]*inv1, o_acc[nt][3]*inv1);
    }
}

// =====================================================================
extern "C" void kernel_launch(void* const* d_in, const int* in_sizes, int n_in,
                              void* d_out, int out_size)
{
    (void)in_sizes; (void)n_in; (void)out_size;
    const float* x  = (const float*)d_in[0];
    const float* Wq = (const float*)d_in[1];
    const float* bq = (const float*)d_in[2];
    const float* Wk = (const float*)d_in[3];
    const float* bk = (const float*)d_in[4];
    const float* Wv = (const float*)d_in[5];
    const float* bv = (const float*)d_in[6];
    const float* Wo = (const float*)d_in[7];
    const float* bo = (const float*)d_in[8];
    float* out = (float*)d_out;

    qkv_gemm_tf32<<<dim3(HK/128, MROWS/128, 3), 256>>>(x, Wq, bq, Wk, bk, Wv, bv);

    cudaFuncSetAttribute(attn_mma, cudaFuncAttributeMaxDynamicSharedMemorySize, ATTN_SMEM);
    attn_mma<<<dim3(S_LEN/128, B_SZ*NH), 256, ATTN_SMEM>>>();

    out_gemm_tf32<<<dim3(DM/128, MROWS/128), 256>>>(Wo, bo, out);
}

// round 4
// speedup vs baseline: 2.2313x; 1.0535x over previous
#include <cuda_runtime.h>

#define S_LEN   2048
#define B_SZ    2
#define DM      1024
#define NH      16
#define HD      64
#define HK      1024            // NH*HD
#define MROWS   (B_SZ*S_LEN)    // 4096

// ---------------- scratch (static device arrays; no allocation) -------------
__device__ float g_q[B_SZ*NH*S_LEN*HD];   // (b,h,s,k) 16 MB
__device__ float g_k[B_SZ*NH*S_LEN*HD];
__device__ float g_v[B_SZ*NH*S_LEN*HD];
__device__ float g_o[MROWS*HK];           // (b,s,hk)  16 MB

// ---------------- tf32 helpers ----------------------------------------------
__device__ __forceinline__ unsigned f2tf32(float f) {
    unsigned r;
    asm("cvt.rna.tf32.f32 %0, %1;" : "=r"(r) : "f"(f));
    return r;
}

__device__ __forceinline__ void mma_tf32(float* c, const unsigned* a, const unsigned* b) {
    asm volatile(
        "mma.sync.aligned.m16n8k8.row.col.f32.tf32.tf32.f32 "
        "{%0,%1,%2,%3}, {%4,%5,%6,%7}, {%8,%9}, {%0,%1,%2,%3};\n"
        : "+f"(c[0]), "+f"(c[1]), "+f"(c[2]), "+f"(c[3])
        : "r"(a[0]), "r"(a[1]), "r"(a[2]), "r"(a[3]),
          "r"(b[0]), "r"(b[1]));
}

// =====================================================================
// TF32 GEMM, 128x128x16 tile, 256 threads (8 warps 4x2), double-buffered.
// =====================================================================
#define GS 132   // smem row stride

#define GEMM_STAGE(buf) do {                                                  \
    As[buf][aCol+0][aRow]    = f2tf32(a0r.x);                                 \
    As[buf][aCol+1][aRow]    = f2tf32(a0r.y);                                 \
    As[buf][aCol+2][aRow]    = f2tf32(a0r.z);                                 \
    As[buf][aCol+3][aRow]    = f2tf32(a0r.w);                                 \
    As[buf][aCol+0][aRow+64] = f2tf32(a1r.x);                                 \
    As[buf][aCol+1][aRow+64] = f2tf32(a1r.y);                                 \
    As[buf][aCol+2][aRow+64] = f2tf32(a1r.z);                                 \
    As[buf][aCol+3][aRow+64] = f2tf32(a1r.w);                                 \
    Bs[buf][bRow][bCol+0]    = f2tf32(b0r.x);                                 \
    Bs[buf][bRow][bCol+1]    = f2tf32(b0r.y);                                 \
    Bs[buf][bRow][bCol+2]    = f2tf32(b0r.z);                                 \
    Bs[buf][bRow][bCol+3]    = f2tf32(b0r.w);                                 \
    Bs[buf][bRow+8][bCol+0]  = f2tf32(b1r.x);                                 \
    Bs[buf][bRow+8][bCol+1]  = f2tf32(b1r.y);                                 \
    Bs[buf][bRow+8][bCol+2]  = f2tf32(b1r.z);                                 \
    Bs[buf][bRow+8][bCol+3]  = f2tf32(b1r.w);                                 \
} while (0)

#define GEMM_MMA(buf) do {                                                    \
    _Pragma("unroll")                                                         \
    for (int ks = 0; ks < 2; ks++) {                                          \
        int kb = ks * 8;                                                      \
        unsigned af[2][4], bf[8][2];                                          \
        _Pragma("unroll")                                                     \
        for (int i = 0; i < 2; i++) {                                         \
            int mb = wm*32 + i*16;                                            \
            af[i][0] = As[buf][kb+tig  ][mb+g];                               \
            af[i][1] = As[buf][kb+tig  ][mb+g+8];                             \
            af[i][2] = As[buf][kb+tig+4][mb+g];                               \
            af[i][3] = As[buf][kb+tig+4][mb+g+8];                             \
        }                                                                     \
        _Pragma("unroll")                                                     \
        for (int j = 0; j < 8; j++) {                                         \
            int nb = wn*64 + j*8;                                             \
            bf[j][0] = Bs[buf][kb+tig  ][nb+g];                               \
            bf[j][1] = Bs[buf][kb+tig+4][nb+g];                               \
        }                                                                     \
        _Pragma("unroll")                                                     \
        for (int i = 0; i < 2; i++)                                           \
            _Pragma("unroll")                                                 \
            for (int j = 0; j < 8; j++)                                       \
                mma_tf32(acc[i][j], af[i], bf[j]);                            \
    }                                                                         \
} while (0)

__global__ __launch_bounds__(256, 2)
void qkv_gemm_tf32(const float* __restrict__ x,
                   const float* __restrict__ Wq, const float* __restrict__ bq,
                   const float* __restrict__ Wk, const float* __restrict__ bk,
                   const float* __restrict__ Wv, const float* __restrict__ bv)
{
    __shared__ unsigned As[2][16][GS];
    __shared__ unsigned Bs[2][16][GS];

    const float* W; const float* bias; float* out;
    int z = blockIdx.z;
    if (z == 0)      { W = Wq; bias = bq; out = g_q; }
    else if (z == 1) { W = Wk; bias = bk; out = g_k; }
    else             { W = Wv; bias = bv; out = g_v; }

    int tid  = threadIdx.x;
    int w    = tid >> 5, lane = tid & 31;
    int g    = lane >> 2, tig = lane & 3;
    int wm   = w & 3, wn = w >> 2;
    int m0   = blockIdx.y * 128, n0 = blockIdx.x * 128;

    int aRow = tid >> 2;
    int aCol = (tid & 3) * 4;
    int bRow = tid >> 5;
    int bCol = (tid & 31) * 4;

    const float* aPtr = x + (size_t)(m0 + aRow) * DM + aCol;
    const float* bPtr = W + (size_t)bRow * HK + n0 + bCol;

    float4 a0r = *(const float4*)aPtr;
    float4 a1r = *(const float4*)(aPtr + (size_t)64 * DM);
    float4 b0r = *(const float4*)bPtr;
    float4 b1r = *(const float4*)(bPtr + (size_t)8 * HK);

    float acc[2][8][4] = {};

    GEMM_STAGE(0);
    __syncthreads();

    for (int k0 = 0; k0 < DM; k0 += 16) {
        int cur = (k0 >> 4) & 1;
        bool more = (k0 + 16 < DM);
        if (more) {
            a0r = *(const float4*)(aPtr + (k0 + 16));
            a1r = *(const float4*)(aPtr + (size_t)64 * DM + (k0 + 16));
            b0r = *(const float4*)(bPtr + (size_t)(k0 + 16) * HK);
            b1r = *(const float4*)(bPtr + (size_t)(k0 + 24) * HK);
        }
        GEMM_MMA(cur);
        if (more) {
            if (cur) GEMM_STAGE(0); else GEMM_STAGE(1);
        }
        __syncthreads();
    }

    #pragma unroll
    for (int i = 0; i < 2; i++) {
        int r0m = m0 + wm*32 + i*16 + g;
        #pragma unroll
        for (int j = 0; j < 8; j++) {
            int n = n0 + wn*64 + j*8 + tig*2;
            int h = n >> 6, kd = n & 63;
            float bv0 = bias[n], bv1 = bias[n+1];
            int b0i = r0m >> 11, s0 = r0m & (S_LEN-1);
            size_t base0 = (((size_t)(b0i*NH + h) * S_LEN + s0) << 6) + kd;
            out[base0]     = acc[i][j][0] + bv0;
            out[base0 + 1] = acc[i][j][1] + bv1;
            int r1m = r0m + 8;
            int b1i = r1m >> 11, s1 = r1m & (S_LEN-1);
            size_t base1 = (((size_t)(b1i*NH + h) * S_LEN + s1) << 6) + kd;
            out[base1]     = acc[i][j][2] + bv0;
            out[base1 + 1] = acc[i][j][3] + bv1;
        }
    }
}

__global__ __launch_bounds__(256, 2)
void out_gemm_tf32(const float* __restrict__ Wo,
                   const float* __restrict__ bo,
                   float* __restrict__ C)
{
    __shared__ unsigned As[2][16][GS];
    __shared__ unsigned Bs[2][16][GS];

    int tid  = threadIdx.x;
    int w    = tid >> 5, lane = tid & 31;
    int g    = lane >> 2, tig = lane & 3;
    int wm   = w & 3, wn = w >> 2;
    int m0   = blockIdx.y * 128, n0 = blockIdx.x * 128;

    int aRow = tid >> 2;
    int aCol = (tid & 3) * 4;
    int bRow = tid >> 5;
    int bCol = (tid & 31) * 4;

    const float* aPtr = g_o + (size_t)(m0 + aRow) * HK + aCol;
    const float* bPtr = Wo + (size_t)bRow * DM + n0 + bCol;

    float4 a0r = *(const float4*)aPtr;
    float4 a1r = *(const float4*)(aPtr + (size_t)64 * HK);
    float4 b0r = *(const float4*)bPtr;
    float4 b1r = *(const float4*)(bPtr + (size_t)8 * DM);

    float acc[2][8][4] = {};

    GEMM_STAGE(0);
    __syncthreads();

    for (int k0 = 0; k0 < HK; k0 += 16) {
        int cur = (k0 >> 4) & 1;
        bool more = (k0 + 16 < HK);
        if (more) {
            a0r = *(const float4*)(aPtr + (k0 + 16));
            a1r = *(const float4*)(aPtr + (size_t)64 * HK + (k0 + 16));
            b0r = *(const float4*)(bPtr + (size_t)(k0 + 16) * DM);
            b1r = *(const float4*)(bPtr + (size_t)(k0 + 24) * DM);
        }
        GEMM_MMA(cur);
        if (more) {
            if (cur) GEMM_STAGE(0); else GEMM_STAGE(1);
        }
        __syncthreads();
    }

    #pragma unroll
    for (int i = 0; i < 2; i++) {
        int r0m = m0 + wm*32 + i*16 + g;
        #pragma unroll
        for (int j = 0; j < 8; j++) {
            int n = n0 + wn*64 + j*8 + tig*2;
            float bv0 = bo[n], bv1 = bo[n+1];
            float2 o0 = make_float2(acc[i][j][0] + bv0, acc[i][j][1] + bv1);
            float2 o1 = make_float2(acc[i][j][2] + bv0, acc[i][j][3] + bv1);
            *(float2*)&C[(size_t)r0m * DM + n]       = o0;
            *(float2*)&C[(size_t)(r0m+8) * DM + n]   = o1;
        }
    }
}

// =====================================================================
// Flash attention on tf32 tensor cores; key tile 64 (smem 64 KB -> 2 CTA/SM).
// Block: 128 q rows of one (b,h), 256 threads (8 warps).
// Warp w owns q rows [16w, 16w+16).
//   KB [8 kt][8 nt][32 lane][2]   (K as B-operand of QK^T)    16 KB
//   VB [8 kt][8 nt][32 lane][2]   (V as B-operand of P@V)     16 KB
//   PA [8 warp][8 kt][32 lane][4] (P as A-operand, warp-priv) 32 KB
// =====================================================================
#define ATTN_SMEM (16384 * 4)   // 64 KB

__global__ __launch_bounds__(256, 2)
void attn_mma()
{
    extern __shared__ unsigned su[];
    unsigned* KB = su;            // 4096
    unsigned* VB = su + 4096;     // 4096
    unsigned* PA = su + 8192;     // 8192

    int tid  = threadIdx.x;
    int w    = tid >> 5, lane = tid & 31;
    int g    = lane >> 2, tig = lane & 3;
    int bh   = blockIdx.y;
    int b    = bh >> 4, h = bh & 15;
    int q0   = blockIdx.x * 128;

    const float* qp = g_q + (size_t)bh * S_LEN * HD;
    const float* kp = g_k + (size_t)bh * S_LEN * HD;
    const float* vp = g_v + (size_t)bh * S_LEN * HD;

    // ---- stage Q tile (overlay on KB+VB), pin fragments in registers ----
    float* Qs = (float*)su;    // [128][64] = 32 KB
    #pragma unroll
    for (int it = 0; it < 8; it++) {
        int linear = it*256 + tid;
        int j = linear >> 4, d0 = (linear & 15) * 4;
        *(float4*)&Qs[j*64 + d0] = *(const float4*)&qp[(size_t)(q0 + j)*HD + d0];
    }
    __syncthreads();
    unsigned qf[8][4];
    #pragma unroll
    for (int kt = 0; kt < 8; kt++) {
        qf[kt][0] = f2tf32(Qs[(16*w+g  )*64 + kt*8 + tig  ]);
        qf[kt][1] = f2tf32(Qs[(16*w+g+8)*64 + kt*8 + tig  ]);
        qf[kt][2] = f2tf32(Qs[(16*w+g  )*64 + kt*8 + tig+4]);
        qf[kt][3] = f2tf32(Qs[(16*w+g+8)*64 + kt*8 + tig+4]);
    }
    __syncthreads();

    float o_acc[8][4] = {};
    float m0 = -1e30f, m1 = -1e30f, l0 = 0.f, l1 = 0.f;

    for (int t0 = 0; t0 < S_LEN; t0 += 64) {
        // ---- stage K, V (64 rows) into fragment layouts ----
        #pragma unroll
        for (int it = 0; it < 4; it++) {
            int linear = it*256 + tid;
            int j = linear >> 4, d0 = (linear & 15) * 4;
            float4 kv = *(const float4*)&kp[(size_t)(t0+j)*HD + d0];
            {
                int kt = d0 >> 3, creg = (d0 >> 2) & 1;
                int nt = j >> 3, nin = j & 7;
                unsigned* dst = &KB[(((kt<<3)+nt)<<6) + (nin<<3) + creg];
                dst[0] = f2tf32(kv.x); dst[2] = f2tf32(kv.y);
                dst[4] = f2tf32(kv.z); dst[6] = f2tf32(kv.w);
            }
            float4 vv = *(const float4*)&vp[(size_t)(t0+j)*HD + d0];
            {
                int ktv = j >> 3, kin = j & 7;
                int ntv = d0 >> 3, nin0 = d0 & 7;      // 0 or 4
                unsigned* dv = &VB[(((ktv<<3)+ntv)<<6) + ((nin0*4 + (kin&3))<<1) + (kin>>2)];
                dv[0]  = f2tf32(vv.x); dv[8]  = f2tf32(vv.y);
                dv[16] = f2tf32(vv.z); dv[24] = f2tf32(vv.w);
            }
        }
        __syncthreads();

        // ---- S = Q @ K^T (16 q rows x 64 keys per warp) ----
        float s[8][4];
        #pragma unroll
        for (int nt = 0; nt < 8; nt++) { s[nt][0]=0.f; s[nt][1]=0.f; s[nt][2]=0.f; s[nt][3]=0.f; }
        #pragma unroll
        for (int kt = 0; kt < 8; kt++) {
            #pragma unroll
            for (int nt = 0; nt < 8; nt++) {
                unsigned b2[2];
                *(uint2*)b2 = *(const uint2*)&KB[(((kt<<3)+nt)<<6) + (lane<<1)];
                mma_tf32(s[nt], qf[kt], b2);
            }
        }

        // ---- online softmax (quad-local) ----
        float mx0 = m0, mx1 = m1;
        #pragma unroll
        for (int nt = 0; nt < 8; nt++) {
            mx0 = fmaxf(mx0, fmaxf(s[nt][0], s[nt][1]) * 0.125f);
            mx1 = fmaxf(mx1, fmaxf(s[nt][2], s[nt][3]) * 0.125f);
        }
        mx0 = fmaxf(mx0, __shfl_xor_sync(0xffffffffu, mx0, 1));
        mx0 = fmaxf(mx0, __shfl_xor_sync(0xffffffffu, mx0, 2));
        mx1 = fmaxf(mx1, __shfl_xor_sync(0xffffffffu, mx1, 1));
        mx1 = fmaxf(mx1, __shfl_xor_sync(0xffffffffu, mx1, 2));

        float alpha0 = __expf(m0 - mx0);
        float alpha1 = __expf(m1 - mx1);
        m0 = mx0; m1 = mx1;

        float sum0 = 0.f, sum1 = 0.f;
        unsigned* paw = PA + w*1024;
        #pragma unroll
        for (int nt = 0; nt < 8; nt++) {
            float p00 = __expf(s[nt][0]*0.125f - mx0);
            float p01 = __expf(s[nt][1]*0.125f - mx0);
            float p10 = __expf(s[nt][2]*0.125f - mx1);
            float p11 = __expf(s[nt][3]*0.125f - mx1);
            sum0 += p00 + p01;
            sum1 += p10 + p11;
            int c0 = 2*tig;
            int regsel = (c0 < 4) ? 0 : 2;
            unsigned* base = &paw[((nt<<5) + 4*g + (c0&3)) * 4 + regsel];
            *(uint2*)base       = make_uint2(f2tf32(p00), f2tf32(p10));
            *(uint2*)(base + 4) = make_uint2(f2tf32(p01), f2tf32(p11));
        }
        sum0 += __shfl_xor_sync(0xffffffffu, sum0, 1);
        sum0 += __shfl_xor_sync(0xffffffffu, sum0, 2);
        sum1 += __shfl_xor_sync(0xffffffffu, sum1, 1);
        sum1 += __shfl_xor_sync(0xffffffffu, sum1, 2);
        l0 = l0*alpha0 + sum0;
        l1 = l1*alpha1 + sum1;

        #pragma unroll
        for (int nt = 0; nt < 8; nt++) {
            o_acc[nt][0] *= alpha0; o_acc[nt][1] *= alpha0;
            o_acc[nt][2] *= alpha1; o_acc[nt][3] *= alpha1;
        }
        __syncwarp();

        // ---- O += P @ V ----
        #pragma unroll
        for (int kt = 0; kt < 8; kt++) {
            unsigned pa[4];
            *(uint4*)pa = *(const uint4*)&paw[((kt<<5) + lane) * 4];
            #pragma unroll
            for (int nt = 0; nt < 8; nt++) {
                unsigned b2[2];
                *(uint2*)b2 = *(const uint2*)&VB[(((kt<<3)+nt)<<6) + (lane<<1)];
                mma_tf32(o_acc[nt], pa, b2);
            }
        }
        __syncthreads();
    }

    // ---- epilogue ----
    float inv0 = 1.0f / l0, inv1 = 1.0f / l1;
    int r0 = q0 + 16*w + g, r1 = r0 + 8;
    #pragma unroll
    for (int nt = 0; nt < 8; nt++) {
        int c = nt*8 + 2*tig;
        *(float2*)&g_o[(size_t)(b*S_LEN + r0)*HK + h*64 + c] =
            make_float2(o_acc[nt][0]*inv0, o_acc[nt][1]*inv0);
        *(float2*)&g_o[(size_t)(b*S_LEN + r1)*HK + h*64 + c] =
            make_float2(o_acc[nt][2]*inv1, o_acc[nt][3]*inv1);
    }
}

// =====================================================================
extern "C" void kernel_launch(void* const* d_in, const int* in_sizes, int n_in,
                              void* d_out, int out_size)
{
    (void)in_sizes; (void)n_in; (void)out_size;
    const float* x  = (const float*)d_in[0];
    const float* Wq = (const float*)d_in[1];
    const float* bq = (const float*)d_in[2];
    const float* Wk = (const float*)d_in[3];
    const float* bk = (const float*)d_in[4];
    const float* Wv = (const float*)d_in[5];
    const float* bv = (const float*)d_in[6];
    const float* Wo = (const float*)d_in[7];
    const float* bo = (const float*)d_in[8];
    float* out = (float*)d_out;

    qkv_gemm_tf32<<<dim3(HK/128, MROWS/128, 3), 256>>>(x, Wq, bq, Wk, bk, Wv, bv);

    cudaFuncSetAttribute(attn_mma, cudaFuncAttributeMaxDynamicSharedMemorySize, ATTN_SMEM);
    attn_mma<<<dim3(S_LEN/128, B_SZ*NH), 256, ATTN_SMEM>>>();

    out_gemm_tf32<<<dim3(DM/128, MROWS/128), 256>>>(Wo, bo, out);
}